// round 14
// baseline (speedup 1.0000x reference)
#include <cuda_runtime.h>

// SC-based GEMM, collapsed analytically:
//   out[m,n] = sum_k min(t1[m,k], t2[k,n]) * e1[m,k] * e2[k,n]
// t = floor(norm*256), e = sign * 2^{-s} (extra /256 folded into e2).
// Valid because rngSeq = arange(L) and the reference's ascending sequence
// are sorted unary prefixes, so popcount(b1 & b2) == min(t1, t2).
//
// SINGLE kernel, warp-split-K, occupancy-2 shape: 256 CTAs x 512 threads
// (one wave at 2 CTAs/SM -> 8 warps/SMSP). Each CTA owns a 16x16 tile;
// 16 warps cover disjoint k-chunks of 16 (full K resident in 64KB smem),
// then reduce warp partials through shared memory. Branchless encode
// (x==0 gives thr=0, zeroing the pair product downstream).

#define MKN 256
#define TM 16            // tile rows (m)
#define TN 16            // tile cols (n)
#define NW 16            // warps per CTA
#define KW 16            // k per warp

// dynamic smem (floats): sAt[256][16] @0, sAe @4096, sBt @8192, sBe @12288
#define OFF_AE 4096
#define OFF_BT 8192
#define OFF_BE 12288
#define SMEM_FLOATS 16384   // 64KB

__device__ __forceinline__ float2 sc_encode(float x, int extra_shift) {
    int xb   = __float_as_int(x);
    int bits = xb & 0x7FFFFFFF;               // |x| bits
    int q    = (bits >> 23) - 126;            // frexp exponent (normals)
    int s    = ((bits & 0x7FFFFF) == 0) ? (1 - q) : (-q);  // floor(-log2|x|)
    s = max(0, min(s, 8));                    // clip to DATA_WIDTH
    // thr = floor(|x| * 2^(s+8)); power-of-2 scale is exact.
    float thr = floorf(__int_as_float(bits) *
                       __int_as_float((127 + s + 8) << 23));
    // e = sign(x) * 2^{-s-extra}: built directly from bits.
    float e = __int_as_float(((127 - s - extra_shift) << 23) |
                             (xb & 0x80000000u));
    return make_float2(thr, e);
}

__global__ __launch_bounds__(512, 2)
void sc_gemm_kernel(const float* __restrict__ A,
                    const float* __restrict__ B,
                    float* __restrict__ out) {
    extern __shared__ float smem[];
    float* sAt = smem;                        // [k][m], row 16 floats
    float* sAe = smem + OFF_AE;
    float* sBt = smem + OFF_BT;               // [k][n], row 16 floats
    float* sBe = smem + OFF_BE;
    float* sPart = smem;                      // tail overlay (16*256 floats)

    const int t    = threadIdx.x;
    const int lane = t & 31;
    const int w    = t >> 5;                  // warp id 0..15
    const int tn   = lane & 7;                // n-group (0..7), 2 n each
    const int tm   = lane >> 3;               // m-group (0..3), 4 m each
    const int m0   = blockIdx.y * TM;
    const int n0   = blockIdx.x * TN;

    // ---- Encode A panel [TM x 256] -> transposed SoA [k][m].
    // m = t&15 (lanes vary m -> consecutive STS), k-chunk = (t>>4)*8.
    {
        int m  = t & 15;
        int kb = (t >> 4) * 8;                // 0..248
        const float* src = A + (m0 + m) * MKN + kb;
        float4 x0 = *(const float4*)src;
        float4 x1 = *(const float4*)(src + 4);
        float xs[8] = {x0.x, x0.y, x0.z, x0.w, x1.x, x1.y, x1.z, x1.w};
        #pragma unroll
        for (int j = 0; j < 8; ++j) {
            float2 en = sc_encode(xs[j], 0);
            sAt[(kb + j) * TM + m] = en.x;
            sAe[(kb + j) * TM + m] = en.y;
        }
    }
    // ---- Encode B panel [256 x TN]: coalesced float4 in, float4 STS out.
    {
        #pragma unroll
        for (int j = 0; j < 2; ++j) {
            int i  = t + j * 512;             // 0..1023 float4 slots
            int k  = i >> 2;                  // 0..255
            int n4 = (i & 3) * 4;             // 0,4,8,12
            float4 x = *(const float4*)(B + k * MKN + n0 + n4);
            float2 e0 = sc_encode(x.x, 8);
            float2 e1 = sc_encode(x.y, 8);
            float2 e2 = sc_encode(x.z, 8);
            float2 e3 = sc_encode(x.w, 8);
            *(float4*)&sBt[k * TN + n4] = make_float4(e0.x, e1.x, e2.x, e3.x);
            *(float4*)&sBe[k * TN + n4] = make_float4(e0.y, e1.y, e2.y, e3.y);
        }
    }
    __syncthreads();

    // ---- Mainloop: this warp's contiguous k-chunk of 16; 4x2 per thread.
    float acc[4][2];
    #pragma unroll
    for (int i = 0; i < 4; ++i) {
        acc[i][0] = 0.0f; acc[i][1] = 0.0f;
    }

    const int kb = w * KW;
    #pragma unroll
    for (int kk = 0; kk < KW; ++kk) {
        int k = kb + kk;
        float4 at = *(const float4*)&sAt[k * TM + tm * 4];  // 4 addrs, x8 bcast
        float4 ae = *(const float4*)&sAe[k * TM + tm * 4];
        float2 bt = *(const float2*)&sBt[k * TN + tn * 2];  // 8 addrs, x4 bcast
        float2 be = *(const float2*)&sBe[k * TN + tn * 2];
        const float* atp = &at.x; const float* aep = &ae.x;
        #pragma unroll
        for (int i = 0; i < 4; ++i) {
            acc[i][0] = fmaf(fminf(atp[i], bt.x) * aep[i], be.x, acc[i][0]);
            acc[i][1] = fmaf(fminf(atp[i], bt.y) * aep[i], be.y, acc[i][1]);
        }
    }

    // ---- Cross-warp reduction via smem overlay on the A region.
    __syncthreads();                          // all mainloop reads done
    #pragma unroll
    for (int i = 0; i < 4; ++i)
        *(float2*)&sPart[w * 256 + (tm * 4 + i) * TN + tn * 2] =
            make_float2(acc[i][0], acc[i][1]);
    __syncthreads();

    // One output per thread (threads 0..255); fixed warp order.
    if (t < 256) {
        float s0 = 0.0f, s1 = 0.0f, s2 = 0.0f, s3 = 0.0f;
        #pragma unroll
        for (int r = 0; r < NW; r += 4) {
            s0 += sPart[(r + 0) * 256 + t];
            s1 += sPart[(r + 1) * 256 + t];
            s2 += sPart[(r + 2) * 256 + t];
            s3 += sPart[(r + 3) * 256 + t];
        }
        int mloc = t >> 4;                    // 0..15
        int nloc = t & 15;                    // 0..15
        out[(m0 + mloc) * MKN + n0 + nloc] = (s0 + s1) + (s2 + s3);
    }
}

extern "C" void kernel_launch(void* const* d_in, const int* in_sizes, int n_in,
                              void* d_out, int out_size) {
    const float* A = (const float*)d_in[0];   // tensor_1 [256,256]
    const float* B = (const float*)d_in[1];   // tensor_2 [256,256]
    // d_in[2] = rngSeq (arange(256)); sortedness folded into the math.
    float* out = (float*)d_out;

    static int configured = 0;                // idempotent attr set (as R13)
    if (!configured) {
        cudaFuncSetAttribute(sc_gemm_kernel,
                             cudaFuncAttributeMaxDynamicSharedMemorySize,
                             SMEM_FLOATS * 4);
        configured = 1;
    }

    dim3 grid(MKN / TN, MKN / TM);            // 16 x 16 = 256 CTAs, one wave
    sc_gemm_kernel<<<grid, 512, SMEM_FLOATS * 4>>>(A, B, out);
}

// round 15
// speedup vs baseline: 1.2316x; 1.2316x over previous
#include <cuda_runtime.h>

// SC-based GEMM, collapsed analytically:
//   out[m,n] = sum_k min(t1[m,k], t2[k,n]) * e1[m,k] * e2[k,n]
// t = floor(norm*256), e = sign * 2^{-s} (extra /256 folded into e2).
// Valid because rngSeq = arange(L) and the reference's ascending sequence
// are sorted unary prefixes, so popcount(b1 & b2) == min(t1, t2).
//
// R13 structure (proven fastest): SINGLE kernel, warp-split-K, full K in
// 96KB dynamic smem, 128 CTAs x 512 threads (one wave), tile 32x16, 4x4
// register tile. New: inner math uses packed f32x2 mul/fma (sm_103a) on
// (j0,j1)/(j2,j3) output pairs, cutting mainloop instructions ~20%.

#define MKN 256
#define TM 32            // tile rows (m)
#define TN 16            // tile cols (n)
#define NW 16            // warps per CTA
#define KW 16            // k per warp (256 / NW)

#define OFF_AE 8192
#define OFF_BT 16384
#define OFF_BE 20480
#define SMEM_FLOATS 24576   // 96KB

typedef unsigned long long u64;

__device__ __forceinline__ float2 sc_encode(float x, int extra_shift) {
    int xb   = __float_as_int(x);
    int bits = xb & 0x7FFFFFFF;               // |x| bits
    int q    = (bits >> 23) - 126;            // frexp exponent (normals)
    int s    = ((bits & 0x7FFFFF) == 0) ? (1 - q) : (-q);  // floor(-log2|x|)
    s = max(0, min(s, 8));                    // clip to DATA_WIDTH
    // thr = floor(|x| * 2^(s+8)); power-of-2 scale is exact.
    float thr = floorf(__int_as_float(bits) *
                       __int_as_float((127 + s + 8) << 23));
    // e = sign(x) * 2^{-s-extra}: built directly from bits.
    float e = __int_as_float(((127 - s - extra_shift) << 23) |
                             (xb & 0x80000000u));
    return make_float2(thr, e);
}

// acc_pair += min(at, {bt0,bt1}) * {ae,ae} * {be0,be1}   (packed f32x2)
__device__ __forceinline__ void sc_pair(u64& acc, float at, float bt0,
                                        float bt1, u64 aed, u64 bed) {
    asm("{\n\t"
        ".reg .f32 lo, hi;\n\t"
        ".reg .b64 p;\n\t"
        "min.f32 lo, %1, %2;\n\t"
        "min.f32 hi, %1, %3;\n\t"
        "mov.b64 p, {lo, hi};\n\t"
        "mul.rn.f32x2 p, p, %4;\n\t"
        "fma.rn.f32x2 %0, p, %5, %0;\n\t"
        "}"
        : "+l"(acc)
        : "f"(at), "f"(bt0), "f"(bt1), "l"(aed), "l"(bed));
}

__global__ __launch_bounds__(512, 1)
void sc_gemm_kernel(const float* __restrict__ A,
                    const float* __restrict__ B,
                    float* __restrict__ out) {
    extern __shared__ float smem[];
    float* sAt = smem;                        // [k][m], row 32 floats
    float* sAe = smem + OFF_AE;
    float* sBt = smem + OFF_BT;               // [k][n], row 16 floats
    float* sBe = smem + OFF_BE;
    float* sPart = smem;                      // tail overlay (16*512 floats)

    const int t    = threadIdx.x;
    const int lane = t & 31;
    const int w    = t >> 5;                  // warp id 0..15
    const int tn   = lane & 3;                // n-group (0..3)
    const int tm   = lane >> 2;               // m-group (0..7)
    const int m0   = blockIdx.y * TM;
    const int n0   = blockIdx.x * TN;

    // ---- Encode A panel [TM x 256] -> transposed SoA [k][m].
    {
        int m  = t & 31;
        int kb = (t >> 5) * 16;
        const float* src = A + (m0 + m) * MKN + kb;
        #pragma unroll
        for (int v = 0; v < 4; ++v) {
            float4 x = *(const float4*)(src + v * 4);
            float xs[4] = {x.x, x.y, x.z, x.w};
            #pragma unroll
            for (int j = 0; j < 4; ++j) {
                float2 en = sc_encode(xs[j], 0);
                int k = kb + v * 4 + j;
                sAt[k * TM + m] = en.x;
                sAe[k * TM + m] = en.y;
            }
        }
    }
    // ---- Encode B panel [256 x TN]: coalesced float4 in, float4 STS out.
    {
        #pragma unroll
        for (int j = 0; j < 2; ++j) {
            int i  = t + j * 512;             // 0..1023 float4 slots
            int k  = i >> 2;                  // 0..255
            int n4 = (i & 3) * 4;             // 0,4,8,12
            float4 x = *(const float4*)(B + k * MKN + n0 + n4);
            float2 e0 = sc_encode(x.x, 8);
            float2 e1 = sc_encode(x.y, 8);
            float2 e2 = sc_encode(x.z, 8);
            float2 e3 = sc_encode(x.w, 8);
            *(float4*)&sBt[k * TN + n4] = make_float4(e0.x, e1.x, e2.x, e3.x);
            *(float4*)&sBe[k * TN + n4] = make_float4(e0.y, e1.y, e2.y, e3.y);
        }
    }
    __syncthreads();

    // ---- Mainloop: this warp's contiguous k-chunk of 16; 4x4 per thread,
    //      packed f32x2 over (j0,j1) and (j2,j3).
    u64 acc01[4] = {0ull, 0ull, 0ull, 0ull};  // (j0,j1) pairs per i
    u64 acc23[4] = {0ull, 0ull, 0ull, 0ull};  // (j2,j3) pairs per i

    const int kb = w * KW;
    #pragma unroll
    for (int kk = 0; kk < KW; ++kk) {
        int k = kb + kk;
        float4 at = *(const float4*)&sAt[k * TM + tm * 4];  // 8 addrs, bcast
        float4 ae = *(const float4*)&sAe[k * TM + tm * 4];
        float4 bt = *(const float4*)&sBt[k * TN + tn * 4];  // 4 addrs, bcast
        ulonglong2 be = *(const ulonglong2*)&sBe[k * TN + tn * 4];
        const float* atp = &at.x; const float* aep = &ae.x;
        u64 aed[4];
        #pragma unroll
        for (int i = 0; i < 4; ++i)
            asm("mov.b64 %0, {%1, %1};" : "=l"(aed[i]) : "f"(aep[i]));
        #pragma unroll
        for (int i = 0; i < 4; ++i) {
            sc_pair(acc01[i], atp[i], bt.x, bt.y, aed[i], be.x);
            sc_pair(acc23[i], atp[i], bt.z, bt.w, aed[i], be.y);
        }
    }

    // ---- Cross-warp reduction via smem overlay on the A region.
    __syncthreads();                          // all mainloop reads done
    #pragma unroll
    for (int i = 0; i < 4; ++i) {
        float f0, f1, f2, f3;
        asm("mov.b64 {%0, %1}, %2;" : "=f"(f0), "=f"(f1) : "l"(acc01[i]));
        asm("mov.b64 {%0, %1}, %2;" : "=f"(f2), "=f"(f3) : "l"(acc23[i]));
        *(float4*)&sPart[w * 512 + (tm * 4 + i) * TN + tn * 4] =
            make_float4(f0, f1, f2, f3);
    }
    __syncthreads();

    // One output per thread; fixed warp order -> deterministic.
    {
        float s0 = 0.0f, s1 = 0.0f, s2 = 0.0f, s3 = 0.0f;
        #pragma unroll
        for (int r = 0; r < NW; r += 4) {
            s0 += sPart[(r + 0) * 512 + t];
            s1 += sPart[(r + 1) * 512 + t];
            s2 += sPart[(r + 2) * 512 + t];
            s3 += sPart[(r + 3) * 512 + t];
        }
        int mloc = t >> 4;                    // 0..31
        int nloc = t & 15;                    // 0..15
        out[(m0 + mloc) * MKN + n0 + nloc] = (s0 + s1) + (s2 + s3);
    }
}

extern "C" void kernel_launch(void* const* d_in, const int* in_sizes, int n_in,
                              void* d_out, int out_size) {
    const float* A = (const float*)d_in[0];   // tensor_1 [256,256]
    const float* B = (const float*)d_in[1];   // tensor_2 [256,256]
    // d_in[2] = rngSeq (arange(256)); sortedness folded into the math.
    float* out = (float*)d_out;

    static int configured = 0;                // idempotent attr set
    if (!configured) {
        cudaFuncSetAttribute(sc_gemm_kernel,
                             cudaFuncAttributeMaxDynamicSharedMemorySize,
                             SMEM_FLOATS * 4);
        configured = 1;
    }

    dim3 grid(MKN / TN, MKN / TM);            // 16 x 8 = 128 CTAs, one wave
    sc_gemm_kernel<<<grid, 512, SMEM_FLOATS * 4>>>(A, B, out);
}